// round 15
// baseline (speedup 1.0000x reference)
#include <cuda_runtime.h>
#include <cstdint>

#define NN      4096
#define IN_DIM  3000
#define H1      512
#define DD      64
#define KSUB    32
#define EDGES   49152
#define HEADS   4
#define NROWS   (NN * HEADS)      // 16384 softmax rows
#define MTILES  64                // 4096/64 m-tiles
#define RECON_ELEMS (NN * IN_DIM)

// ---------------- scratch (device globals; no allocations allowed) ----------------
__device__ float g_deg[NN];
__device__ float g_inv[NN];
__device__ float g_hsplit[4 * NN * H1];
__device__ float g_hlin[NN * H1];
__device__ float g_agg1[NN * H1];
__device__ float g_h[NN * H1];
__device__ float g_slin[NN * DD];
__device__ float g_agg2[NN * DD];
__device__ float g_spot[NN * DD];
__device__ float g_local[NN * DD];
__device__ float g_hdec[NN * H1];
__device__ float g_qkv[NN * 3 * DD];
__device__ float g_scores[(size_t)HEADS * NN * NN];   // [n][h][m]: ((n*4+h)*4096+m)
__device__ float g_attnw[(size_t)NN * NN];
__device__ float g_pmax[MTILES * NROWS];
__device__ float g_psum[MTILES * NROWS];
__device__ float g_rmax[NROWS];
__device__ float g_rsum[NROWS];
__device__ float g_attnpre[NN * DD];
__device__ float g_global[NN * DD];
__device__ int   g_randidx[NN];
__device__ int   g_sampled[NN];

// ---------------- f32x2 packed helpers (sm_103a) ----------------
__device__ __forceinline__ unsigned long long splat2(float x) {
    unsigned long long r;
    asm("mov.b64 %0, {%1, %1};" : "=l"(r) : "f"(x));
    return r;
}
__device__ __forceinline__ void fma2(unsigned long long& d, unsigned long long a, unsigned long long b) {
    asm("fma.rn.f32x2 %0, %1, %2, %0;" : "+l"(d) : "l"(a), "l"(b));
}
__device__ __forceinline__ float2 unpack2(unsigned long long v) {
    float lo, hi;
    asm("mov.b64 {%0, %1}, %2;" : "=f"(lo), "=f"(hi) : "l"(v));
    return make_float2(lo, hi);
}

// ---------------- utility ----------------
__global__ void zero_kernel(float* p, int count) {
    int i = blockIdx.x * blockDim.x + threadIdx.x;
    for (; i < count; i += gridDim.x * blockDim.x) p[i] = 0.f;
}

// split-K reduce over 4 partials (deterministic order)
__global__ void addquad_kernel(const float* __restrict__ s, float* __restrict__ d, int count4) {
    int i = blockIdx.x * blockDim.x + threadIdx.x;
    if (i >= count4) return;
    const float4* a = reinterpret_cast<const float4*>(s);
    float4 x = a[i], y = a[i + count4], z = a[i + 2 * count4], w = a[i + 3 * count4];
    reinterpret_cast<float4*>(d)[i] = make_float4(((x.x + y.x) + z.x) + w.x,
                                                  ((x.y + y.y) + z.y) + w.y,
                                                  ((x.z + y.z) + z.z) + w.z,
                                                  ((x.w + y.w) + z.w) + w.w);
}

// ---------------- GCN degree ----------------
__global__ void deg_kernel(const int* __restrict__ ei, float* __restrict__ deg) {
    int i = blockIdx.x * blockDim.x + threadIdx.x;
    if (i < EDGES) atomicAdd(&deg[ei[EDGES + i]], 1.0f);
}
__global__ void inv_kernel(const float* __restrict__ deg, float* __restrict__ inv) {
    int i = blockIdx.x * blockDim.x + threadIdx.x;
    if (i < NN) inv[i] = rsqrtf(deg[i] + 1.0f);
}

// ---------------- high-throughput fp32x2 GEMM, optional split-K via gridDim.z ----------------
// C_z = A[M, klo:khi] * B[klo:khi, N] (+bias)(+relu), partial z written at C + z*M*N.
// BM=128, 256 threads. M%128==0, N%4==0, K%4==0, ksplit%16==0.
template<int BN, int TM, int TN, bool BIAS, bool RELU>
__global__ __launch_bounds__(256) void gemm_tc(
    const float* __restrict__ A, const float* __restrict__ B,
    const float* __restrict__ bias, float* __restrict__ C,
    int M, int N, int Kd, int ksplit)
{
    constexpr int BM = 128;
    constexpr int KS = 16;
    __shared__ __align__(16) float As[KS][BM + 4];
    __shared__ __align__(16) float Bs[KS][BN + 4];
    const int tid = threadIdx.x;
    const int mb = blockIdx.y * BM, nb = blockIdx.x * BN;
    const int tx = tid % (BN / TN);
    const int ty = tid / (BN / TN);
    const int klo = blockIdx.z * ksplit;
    const int khi = (klo + ksplit < Kd) ? (klo + ksplit) : Kd;
    float* Cw = C + (size_t)blockIdx.z * M * N;

    const int arow = tid >> 1;
    const int akseg = (tid & 1) * 8;
    const int bkk = tid >> 4;
    const int bcol = (tid & 15) * (BN / 16);
    constexpr int BVEC = BN / 64;

    unsigned long long acc2[TM / 2][TN] = {};

    for (int kb = klo; kb < khi; kb += KS) {
        #pragma unroll
        for (int v = 0; v < 2; v++) {
            int kk = akseg + v * 4;
            float4 va = make_float4(0.f, 0.f, 0.f, 0.f);
            if (kb + kk + 4 <= khi)
                va = *reinterpret_cast<const float4*>(A + (size_t)(mb + arow) * Kd + kb + kk);
            As[kk + 0][arow] = va.x;
            As[kk + 1][arow] = va.y;
            As[kk + 2][arow] = va.z;
            As[kk + 3][arow] = va.w;
        }
        #pragma unroll
        for (int v = 0; v < BVEC; v++) {
            int col = bcol + v * 4;
            float4 vb = make_float4(0.f, 0.f, 0.f, 0.f);
            if (kb + bkk < khi && nb + col < N)
                vb = *reinterpret_cast<const float4*>(B + (size_t)(kb + bkk) * N + nb + col);
            *reinterpret_cast<float4*>(&Bs[bkk][col]) = vb;
        }
        __syncthreads();

        #pragma unroll
        for (int kk = 0; kk < KS; kk++) {
            unsigned long long a2[TM / 2];
            #pragma unroll
            for (int i = 0; i < TM; i += 4) {
                ulonglong2 t = *reinterpret_cast<const ulonglong2*>(&As[kk][ty * TM + i]);
                a2[i / 2] = t.x;
                a2[i / 2 + 1] = t.y;
            }
            #pragma unroll
            for (int j = 0; j < TN; j += 4) {
                float4 t = *reinterpret_cast<const float4*>(&Bs[kk][tx * TN + j]);
                unsigned long long b0 = splat2(t.x), b1 = splat2(t.y);
                unsigned long long b2 = splat2(t.z), b3 = splat2(t.w);
                #pragma unroll
                for (int p = 0; p < TM / 2; p++) {
                    fma2(acc2[p][j + 0], a2[p], b0);
                    fma2(acc2[p][j + 1], a2[p], b1);
                    fma2(acc2[p][j + 2], a2[p], b2);
                    fma2(acc2[p][j + 3], a2[p], b3);
                }
            }
        }
        __syncthreads();
    }

    float accf[TM][TN];
    #pragma unroll
    for (int p = 0; p < TM / 2; p++)
        #pragma unroll
        for (int j = 0; j < TN; j++) {
            float2 f = unpack2(acc2[p][j]);
            accf[2 * p][j] = f.x;
            accf[2 * p + 1][j] = f.y;
        }

    #pragma unroll
    for (int i = 0; i < TM; i++) {
        int row = mb + ty * TM + i;
        #pragma unroll
        for (int j = 0; j < TN; j += 4) {
            int col = nb + tx * TN + j;
            if (col < N) {
                float4 v;
                v.x = accf[i][j];     v.y = accf[i][j + 1];
                v.z = accf[i][j + 2]; v.w = accf[i][j + 3];
                if (BIAS) {
                    float4 bsv = *reinterpret_cast<const float4*>(bias + col);
                    v.x += bsv.x; v.y += bsv.y; v.z += bsv.z; v.w += bsv.w;
                }
                if (RELU) {
                    v.x = fmaxf(v.x, 0.f); v.y = fmaxf(v.y, 0.f);
                    v.z = fmaxf(v.z, 0.f); v.w = fmaxf(v.w, 0.f);
                }
                *reinterpret_cast<float4*>(Cw + (size_t)row * N + col) = v;
            }
        }
    }
}

// ---------------- small generic tiled fp32 GEMM (N=64 GCN-2) ----------------
template<bool BIAS, bool RELU>
__global__ __launch_bounds__(256) void gemm_kernel(
    const float* __restrict__ A, const float* __restrict__ B,
    const float* __restrict__ bias, float* __restrict__ C,
    int M, int N, int Kd)
{
    __shared__ float As[16][65];
    __shared__ float Bs[16][64];
    int tid = threadIdx.x;
    int mb = blockIdx.y * 64, nb = blockIdx.x * 64;
    int tx = tid & 15, ty = tid >> 4;
    float acc[4][4] = {};
    for (int kb = 0; kb < Kd; kb += 16) {
        #pragma unroll
        for (int p = 0; p < 4; p++) {
            int idx = tid + p * 256;
            int m = idx >> 4, k = idx & 15;
            float v = 0.f;
            if (kb + k < Kd) v = A[(size_t)(mb + m) * Kd + kb + k];
            As[k][m] = v;
        }
        #pragma unroll
        for (int p = 0; p < 4; p++) {
            int idx = tid + p * 256;
            int k = idx >> 6, nn2 = idx & 63;
            float v = 0.f;
            if (kb + k < Kd && nb + nn2 < N) v = B[(size_t)(kb + k) * N + nb + nn2];
            Bs[k][nn2] = v;
        }
        __syncthreads();
        #pragma unroll
        for (int kk = 0; kk < 16; kk++) {
            float ra[4], rb[4];
            #pragma unroll
            for (int i = 0; i < 4; i++) ra[i] = As[kk][ty * 4 + i];
            #pragma unroll
            for (int j = 0; j < 4; j++) rb[j] = Bs[kk][tx * 4 + j];
            #pragma unroll
            for (int i = 0; i < 4; i++)
                #pragma unroll
                for (int j = 0; j < 4; j++)
                    acc[i][j] += ra[i] * rb[j];
        }
        __syncthreads();
    }
    #pragma unroll
    for (int i = 0; i < 4; i++) {
        int row = mb + ty * 4 + i;
        #pragma unroll
        for (int j = 0; j < 4; j++) {
            int col = nb + tx * 4 + j;
            if (col < N) {
                float v = acc[i][j];
                if (BIAS) v += bias[col];
                if (RELU) v = fmaxf(v, 0.f);
                C[(size_t)row * N + col] = v;
            }
        }
    }
}

// ---------------- edge aggregation (atomics) ----------------
__global__ void agg_edge_kernel(const int* __restrict__ ei, const float* __restrict__ hlin,
                                const float* __restrict__ inv, float* __restrict__ agg, int Hd) {
    int e = blockIdx.x;
    int s = ei[e], d2 = ei[EDGES + e];
    float c = inv[s] * inv[d2];
    const float* hr = hlin + (size_t)s * Hd;
    float* ar = agg + (size_t)d2 * Hd;
    for (int d = threadIdx.x; d < Hd; d += blockDim.x) atomicAdd(&ar[d], hr[d] * c);
}

template<bool RELU>
__global__ void combine_kernel(const float* __restrict__ agg, const float* __restrict__ hlin,
                               const float* __restrict__ inv, const float* __restrict__ bias,
                               float* __restrict__ out, int Hd) {
    int idx = blockIdx.x * blockDim.x + threadIdx.x;
    int total = NN * Hd;
    if (idx >= total) return;
    int n = idx / Hd, d = idx - n * Hd;
    float iv = inv[n];
    float v = agg[idx] + hlin[idx] * iv * iv + bias[d];
    if (RELU) v = fmaxf(v, 0.f);
    out[idx] = v;
}

// ---------------- niche mean pool ----------------
__global__ void niche_kernel(const int* __restrict__ sub, const float* __restrict__ spot,
                             float* __restrict__ local) {
    int n = blockIdx.x, d = threadIdx.x;
    float acc = 0.f;
    #pragma unroll
    for (int k = 0; k < KSUB; k++) {
        int idx = sub[n * KSUB + k];
        acc += spot[(size_t)idx * DD + d];
    }
    local[(size_t)n * DD + d] = acc * (1.0f / KSUB);
}

// ---------------- small linear (out = in @ W^T + b), W is [OUTD,64] row-major ----------------
__global__ void lin_t_kernel(const float* __restrict__ in, const float* __restrict__ W,
                             const float* __restrict__ b, float* __restrict__ out, int OUTD) {
    int nb = blockIdx.x * 32;
    int tid = threadIdx.x;  // OUTD threads
    __shared__ float xl[32][65];
    for (int i = tid; i < 32 * 64; i += blockDim.x)
        xl[i >> 6][i & 63] = in[(size_t)(nb + (i >> 6)) * 64 + (i & 63)];
    __syncthreads();
    float acc[32];
    #pragma unroll
    for (int nn2 = 0; nn2 < 32; nn2++) acc[nn2] = 0.f;
    for (int dd = 0; dd < 64; dd++) {
        float w = W[tid * 64 + dd];
        #pragma unroll
        for (int nn2 = 0; nn2 < 32; nn2++) acc[nn2] += xl[nn2][dd] * w;
    }
    float bb = b[tid];
    #pragma unroll
    for (int nn2 = 0; nn2 < 32; nn2++)
        out[(size_t)(nb + nn2) * OUTD + tid] = acc[nn2] + bb;
}

// ---------------- attention scores + per-tile (max, expsum) partials ----------------
__global__ __launch_bounds__(256) void scores_kernel(const float* __restrict__ qkv,
                                                     float* __restrict__ scores,
                                                     float* __restrict__ pmax,
                                                     float* __restrict__ psum) {
    int h = blockIdx.z;
    int qb = blockIdx.y * 64, mb = blockIdx.x * 64;
    __shared__ float qs[16][65], ks[16][65];
    int tid = threadIdx.x;
    #pragma unroll
    for (int p = 0; p < 4; p++) {
        int idx = tid + p * 256;
        int row = idx >> 4, kk = idx & 15;
        qs[kk][row] = qkv[(size_t)(qb + row) * 192 + h * 16 + kk];
        ks[kk][row] = qkv[(size_t)(mb + row) * 192 + 64 + h * 16 + kk];
    }
    __syncthreads();
    int tx = tid & 15, ty = tid >> 4;
    float acc[4][4] = {};
    #pragma unroll
    for (int kk = 0; kk < 16; kk++) {
        float ra[4], rb[4];
        #pragma unroll
        for (int i = 0; i < 4; i++) ra[i] = qs[kk][ty * 4 + i];
        #pragma unroll
        for (int j = 0; j < 4; j++) rb[j] = ks[kk][tx * 4 + j];
        #pragma unroll
        for (int i = 0; i < 4; i++)
            #pragma unroll
            for (int j = 0; j < 4; j++)
                acc[i][j] += ra[i] * rb[j];
    }
    #pragma unroll
    for (int i = 0; i < 4; i++) {
        float rmx = -1e30f;
        #pragma unroll
        for (int j = 0; j < 4; j++) {
            float s = acc[i][j] * 0.25f;
            acc[i][j] = s;
            rmx = fmaxf(rmx, s);
            scores[((size_t)(qb + ty * 4 + i) * 4 + h) * 4096 + mb + tx * 4 + j] = s;
        }
        // reduce max over the 16 tx lanes (xor on bits 0..3 stays within the tx group)
        #pragma unroll
        for (int off = 8; off > 0; off >>= 1)
            rmx = fmaxf(rmx, __shfl_xor_sync(0xffffffffu, rmx, off));
        float es = 0.f;
        #pragma unroll
        for (int j = 0; j < 4; j++) es += __expf(acc[i][j] - rmx);
        #pragma unroll
        for (int off = 8; off > 0; off >>= 1)
            es += __shfl_xor_sync(0xffffffffu, es, off);
        if (tx == 0) {
            int row = (qb + ty * 4 + i) * 4 + h;
            pmax[blockIdx.x * NROWS + row] = rmx;
            psum[blockIdx.x * NROWS + row] = es;
        }
    }
}

// ---------------- merge per-tile partials -> exact rmax + denominator ----------------
__global__ void smcombine_kernel(const float* __restrict__ pmax, const float* __restrict__ psum,
                                 float* __restrict__ rmax, float* __restrict__ rsum) {
    int row = blockIdx.x * blockDim.x + threadIdx.x;
    if (row >= NROWS) return;
    float M = -1e30f;
    #pragma unroll 8
    for (int t = 0; t < MTILES; t++) M = fmaxf(M, pmax[t * NROWS + row]);
    float S = 0.f;
    #pragma unroll 8
    for (int t = 0; t < MTILES; t++)
        S += psum[t * NROWS + row] * __expf(pmax[t * NROWS + row] - M);
    rmax[row] = M;
    rsum[row] = S;
}

// ---------------- fused probs + attn_w + AV (exp on the fly from raw scores) ----------------
__global__ __launch_bounds__(256) void probav_kernel(
    const float* __restrict__ qkv, const float* __restrict__ scores,
    const float* __restrict__ rmax, const float* __restrict__ rsum,
    float* __restrict__ attnw, float* __restrict__ attnpre)
{
    int qb = blockIdx.x * 16;
    int tid = threadIdx.x;
    __shared__ float vs[64][65];
    __shared__ float ps[16 * 4 * 64];   // [q][h][m]
    __shared__ float rm[64], ri[64];
    if (tid < 64) {
        int q = tid >> 2, h2 = tid & 3;
        rm[q * 4 + h2] = rmax[(qb + q) * 4 + h2];
        ri[q * 4 + h2] = 1.0f / rsum[(qb + q) * 4 + h2];
    }
    int d = tid & 63, g = tid >> 6;
    int h = d >> 4;
    float acc[4] = {0.f, 0.f, 0.f, 0.f};
    __syncthreads();
    for (int mb = 0; mb < 4096; mb += 64) {
        #pragma unroll
        for (int p = 0; p < 16; p++) {
            int i = tid + p * 256;
            vs[i >> 6][i & 63] = qkv[(size_t)(mb + (i >> 6)) * 192 + 128 + (i & 63)];
        }
        int m = tid & 63;
        #pragma unroll
        for (int j = 0; j < 4; j++) {
            int q = j * 4 + (tid >> 6);
            float aw = 0.f;
            #pragma unroll
            for (int hh = 0; hh < 4; hh++) {
                float s = scores[((size_t)(qb + q) * 4 + hh) * 4096 + mb + m];
                float p = __expf(s - rm[q * 4 + hh]) * ri[q * 4 + hh];
                ps[(q * 4 + hh) * 64 + m] = p;
                aw += p;
            }
            attnw[(size_t)(qb + q) * 4096 + mb + m] = aw * 0.25f;
        }
        __syncthreads();
        #pragma unroll 4
        for (int mm = 0; mm < 64; mm++) {
            float v = vs[mm][d];
            #pragma unroll
            for (int i = 0; i < 4; i++)
                acc[i] += ps[((i * 4 + g) * 4 + h) * 64 + mm] * v;
        }
        __syncthreads();
    }
    #pragma unroll
    for (int i = 0; i < 4; i++)
        attnpre[(size_t)(qb + i * 4 + g) * 64 + d] = acc[i];
}

// ---------------- threefry2x32 (matches JAX) ----------------
__device__ __forceinline__ unsigned rotl32(unsigned x, int r) { return (x << r) | (x >> (32 - r)); }
__device__ void threefry2x32(unsigned ks0, unsigned ks1, unsigned& x0, unsigned& x1) {
    unsigned ks2 = 0x1BD11BDAu ^ ks0 ^ ks1;
    x0 += ks0; x1 += ks1;
#define TFR(r) { x0 += x1; x1 = rotl32(x1, r); x1 ^= x0; }
    TFR(13) TFR(15) TFR(26) TFR(6)
    x0 += ks1; x1 += ks2 + 1u;
    TFR(17) TFR(29) TFR(16) TFR(24)
    x0 += ks2; x1 += ks0 + 2u;
    TFR(13) TFR(15) TFR(26) TFR(6)
    x0 += ks0; x1 += ks1 + 3u;
    TFR(17) TFR(29) TFR(16) TFR(24)
    x0 += ks1; x1 += ks2 + 4u;
    TFR(13) TFR(15) TFR(26) TFR(6)
    x0 += ks2; x1 += ks0 + 5u;
#undef TFR
}

// rand_idx = jax.random.randint(key(42), (4096,), 0, 1024)
__global__ void randidx_kernel(int* __restrict__ out) {
    int i = blockIdx.x * blockDim.x + threadIdx.x;
    if (i >= NN) return;
    unsigned a0 = 0u, b0 = 2u; threefry2x32(0u, 42u, a0, b0);
    unsigned a1 = 1u, b1 = 3u; threefry2x32(0u, 42u, a1, b1);
    unsigned k2a = b0, k2b = b1;
    unsigned x0, x1;
    if (i < 2048) { x0 = (unsigned)i; x1 = (unsigned)(i + 2048); }
    else          { x0 = (unsigned)(i - 2048); x1 = (unsigned)i; }
    threefry2x32(k2a, k2b, x0, x1);
    unsigned bits = (i < 2048) ? x0 : x1;
    out[i] = (int)(bits & 1023u);
}

// ---------------- per-row rank-select (radix select on float bits, stable ties) ----------------
__global__ __launch_bounds__(256) void select_kernel(const float* __restrict__ attnw,
                                                     const int* __restrict__ ridx,
                                                     int* __restrict__ sampled) {
    int n = blockIdx.x;
    int tid = threadIdx.x;  // 256
    __shared__ unsigned sk[4096];
    __shared__ int hist[256];
    __shared__ int bcast[2];
    __shared__ int warpcnt[8];
    __shared__ int running;
    const float* row = attnw + (size_t)n * 4096;
    for (int i = tid; i < 4096; i += 256) sk[i] = __float_as_uint(row[i]);
    int rr = ridx[n];
    unsigned prefix = 0;
    __syncthreads();
    for (int shift = 24; shift >= 0; shift -= 8) {
        hist[tid] = 0;
        __syncthreads();
        for (int i = tid; i < 4096; i += 256) {
            unsigned u = sk[i];
            bool match = (shift == 24) || ((u >> (shift + 8)) == prefix);
            if (match) atomicAdd(&hist[(u >> shift) & 255], 1);
        }
        __syncthreads();
        if (tid == 0) {
            int cum = 0; int b = 0;
            for (; b < 256; b++) { int c = hist[b]; if (cum + c > rr) break; cum += c; }
            bcast[0] = b; bcast[1] = rr - cum;
        }
        __syncthreads();
        prefix = (prefix << 8) | (unsigned)bcast[0];
        rr = bcast[1];
        __syncthreads();
    }
    if (tid == 0) running = 0;
    __syncthreads();
    int lane = tid & 31, wid = tid >> 5;
    for (int base = 0; base < 4096; base += 256) {
        int i = base + tid;
        bool m2 = (sk[i] == prefix);
        unsigned bal = __ballot_sync(0xffffffffu, m2);
        if (lane == 0) warpcnt[wid] = __popc(bal);
        __syncthreads();
        int wpre = 0, tot = 0;
        #pragma unroll
        for (int w = 0; w < 8; w++) { int c = warpcnt[w]; if (w < wid) wpre += c; tot += c; }
        int ord = running + wpre + __popc(bal & ((1u << lane) - 1u));
        if (m2 && ord == rr) sampled[n] = i;
        __syncthreads();
        if (tid == 0) running += tot;
        __syncthreads();
    }
}

// ---------------- bilinear discriminator logits ----------------
__global__ void bilinear_kernel(const float* __restrict__ local, const float* __restrict__ bw,
                                const float* __restrict__ bb, const float* __restrict__ glob,
                                const int* __restrict__ sampled,
                                float* __restrict__ lpos, float* __restrict__ lneg) {
    int n = blockIdx.x, e = threadIdx.x;  // 64
    __shared__ float l[64], red[64];
    l[e] = local[(size_t)n * 64 + e];
    __syncthreads();
    float t = 0.f;
    #pragma unroll
    for (int dd = 0; dd < 64; dd++) t += l[dd] * bw[dd * 64 + e];
    int s = sampled[n];
    float p = t * glob[(size_t)n * 64 + e];
    float q = t * glob[(size_t)s * 64 + e];
    red[e] = p; __syncthreads();
    for (int off = 32; off > 0; off >>= 1) { if (e < off) red[e] += red[e + off]; __syncthreads(); }
    if (e == 0) lpos[n] = red[0] + bb[0];
    __syncthreads();
    red[e] = q; __syncthreads();
    for (int off = 32; off > 0; off >>= 1) { if (e < off) red[e] += red[e + off]; __syncthreads(); }
    if (e == 0) lneg[n] = red[0] + bb[0];
}

// ---------------- launcher ----------------
extern "C" void kernel_launch(void* const* d_in, const int* in_sizes, int n_in,
                              void* d_out, int out_size) {
    const float* x    = (const float*)d_in[0];
    const int*   ei   = (const int*)d_in[1];
    const int*   sub  = (const int*)d_in[2];
    const float* ew1  = (const float*)d_in[3];
    const float* eb1  = (const float*)d_in[4];
    const float* ew2  = (const float*)d_in[5];
    const float* eb2  = (const float*)d_in[6];
    const float* dw1  = (const float*)d_in[7];
    const float* db1  = (const float*)d_in[8];
    const float* dw2  = (const float*)d_in[9];
    const float* db2  = (const float*)d_in[10];
    const float* aiw  = (const float*)d_in[11];
    const float* aib  = (const float*)d_in[12];
    const float* aow  = (const float*)d_in[13];
    const float* aob  = (const float*)d_in[14];
    const float* bw   = (const float*)d_in[15];
    const float* bb   = (const float*)d_in[16];

    float* out   = (float*)d_out;
    float* recon = out;
    float* lpos  = out + (size_t)RECON_ELEMS;
    float* lneg  = out + (size_t)RECON_ELEMS + NN;

    float *p_deg, *p_inv, *p_hsplit, *p_hlin, *p_agg1, *p_h, *p_slin, *p_agg2, *p_spot, *p_local;
    float *p_hdec, *p_qkv, *p_scores, *p_attnw, *p_pmax, *p_psum, *p_rmax, *p_rsum;
    float *p_attnpre, *p_global;
    int *p_ridx, *p_samp;
    cudaGetSymbolAddress((void**)&p_deg, g_deg);
    cudaGetSymbolAddress((void**)&p_inv, g_inv);
    cudaGetSymbolAddress((void**)&p_hsplit, g_hsplit);
    cudaGetSymbolAddress((void**)&p_hlin, g_hlin);
    cudaGetSymbolAddress((void**)&p_agg1, g_agg1);
    cudaGetSymbolAddress((void**)&p_h, g_h);
    cudaGetSymbolAddress((void**)&p_slin, g_slin);
    cudaGetSymbolAddress((void**)&p_agg2, g_agg2);
    cudaGetSymbolAddress((void**)&p_spot, g_spot);
    cudaGetSymbolAddress((void**)&p_local, g_local);
    cudaGetSymbolAddress((void**)&p_hdec, g_hdec);
    cudaGetSymbolAddress((void**)&p_qkv, g_qkv);
    cudaGetSymbolAddress((void**)&p_scores, g_scores);
    cudaGetSymbolAddress((void**)&p_attnw, g_attnw);
    cudaGetSymbolAddress((void**)&p_pmax, g_pmax);
    cudaGetSymbolAddress((void**)&p_psum, g_psum);
    cudaGetSymbolAddress((void**)&p_rmax, g_rmax);
    cudaGetSymbolAddress((void**)&p_rsum, g_rsum);
    cudaGetSymbolAddress((void**)&p_attnpre, g_attnpre);
    cudaGetSymbolAddress((void**)&p_global, g_global);
    cudaGetSymbolAddress((void**)&p_ridx, g_randidx);
    cudaGetSymbolAddress((void**)&p_samp, g_sampled);

    // launches 1..3: zero accumulators (every replay)
    zero_kernel<<<4096, 256>>>(p_agg1, NN * H1);
    zero_kernel<<<1024, 256>>>(p_agg2, NN * DD);
    zero_kernel<<<16, 256>>>(p_deg, NN);

    // launch 4 (profiled slot): encoder GEMM, BN=128 fat tile, split-K=4 (512 CTAs)
    gemm_tc<128, 8, 8, false, false><<<dim3(H1 / 128, NN / 128, 4), 256>>>(
        x, ew1, nullptr, p_hsplit, NN, H1, IN_DIM, 752);
    addquad_kernel<<<(NN * H1 / 4 + 255) / 256, 256>>>(p_hsplit, p_hlin, NN * H1 / 4);

    // degrees
    deg_kernel<<<(EDGES + 255) / 256, 256>>>(ei, p_deg);
    inv_kernel<<<(NN + 255) / 256, 256>>>(p_deg, p_inv);

    // GCN layer 1 aggregation
    agg_edge_kernel<<<EDGES, 128>>>(ei, p_hlin, p_inv, p_agg1, H1);
    combine_kernel<true><<<(NN * H1 + 255) / 256, 256>>>(p_agg1, p_hlin, p_inv, eb1, p_h, H1);

    // GCN layer 2
    gemm_kernel<false, false><<<dim3(1, NN / 64), 256>>>(p_h, ew2, nullptr, p_slin, NN, DD, H1);
    agg_edge_kernel<<<EDGES, 64>>>(ei, p_slin, p_inv, p_agg2, DD);
    combine_kernel<false><<<(NN * DD + 255) / 256, 256>>>(p_agg2, p_slin, p_inv, eb2, p_spot, DD);

    // niche mean pool
    niche_kernel<<<NN, DD>>>(sub, p_spot, p_local);

    // decoder
    gemm_tc<64, 8, 4, true, true><<<dim3(H1 / 64, NN / 128, 1), 256>>>(
        p_local, dw1, db1, p_hdec, NN, H1, DD, DD);
    gemm_tc<128, 8, 8, true, false><<<dim3((IN_DIM + 127) / 128, NN / 128, 1), 256>>>(
        p_hdec, dw2, db2, recon, NN, IN_DIM, H1, H1);

    // attention (materialized scores; per-tile softmax partials, no 256MB sum pass)
    lin_t_kernel<<<NN / 32, 192>>>(p_local, aiw, aib, p_qkv, 192);
    scores_kernel<<<dim3(64, 64, 4), 256>>>(p_qkv, p_scores, p_pmax, p_psum);
    smcombine_kernel<<<(NROWS + 255) / 256, 256>>>(p_pmax, p_psum, p_rmax, p_rsum);
    probav_kernel<<<NN / 16, 256>>>(p_qkv, p_scores, p_rmax, p_rsum, p_attnw, p_attnpre);
    lin_t_kernel<<<NN / 32, 64>>>(p_attnpre, aow, aob, p_global, 64);

    // negative sampling + logits
    randidx_kernel<<<(NN + 255) / 256, 256>>>(p_ridx);
    select_kernel<<<NN, 256>>>(p_attnw, p_ridx, p_samp);
    bilinear_kernel<<<NN, 64>>>(p_local, bw, bb, p_global, p_samp, lpos, lneg);
}

// round 17
// speedup vs baseline: 1.1298x; 1.1298x over previous
#include <cuda_runtime.h>
#include <cstdint>

#define NN      4096
#define IN_DIM  3000
#define H1      512
#define DD      64
#define KSUB    32
#define EDGES   49152
#define HEADS   4
#define NROWS   (NN * HEADS)      // 16384 softmax rows
#define MTILES  64                // 4096/64 m-tiles
#define RECON_ELEMS (NN * IN_DIM)

// ---------------- scratch (device globals; no allocations allowed) ----------------
__device__ float g_deg[NN];
__device__ float g_inv[NN];
__device__ float g_hsplit[2 * NN * H1];
__device__ float g_hlin[NN * H1];
__device__ float g_agg1[NN * H1];
__device__ float g_h[NN * H1];
__device__ float g_slin[NN * DD];
__device__ float g_agg2[NN * DD];
__device__ float g_spot[NN * DD];
__device__ float g_local[NN * DD];
__device__ float g_hdec[NN * H1];
__device__ float g_qkv[NN * 3 * DD];
__device__ float g_scores[(size_t)HEADS * NN * NN];   // [n][h][m]: ((n*4+h)*4096+m)
__device__ float g_attnw[(size_t)NN * NN];
__device__ float g_pmax[MTILES * NROWS];
__device__ float g_psum[MTILES * NROWS];
__device__ float g_rmax[NROWS];
__device__ float g_rsum[NROWS];
__device__ float g_attnpre[NN * DD];
__device__ float g_global[NN * DD];
__device__ int   g_randidx[NN];
__device__ int   g_sampled[NN];

// ---------------- f32x2 packed helpers (sm_103a) ----------------
__device__ __forceinline__ unsigned long long splat2(float x) {
    unsigned long long r;
    asm("mov.b64 %0, {%1, %1};" : "=l"(r) : "f"(x));
    return r;
}
__device__ __forceinline__ void fma2(unsigned long long& d, unsigned long long a, unsigned long long b) {
    asm("fma.rn.f32x2 %0, %1, %2, %0;" : "+l"(d) : "l"(a), "l"(b));
}
__device__ __forceinline__ float2 unpack2(unsigned long long v) {
    float lo, hi;
    asm("mov.b64 {%0, %1}, %2;" : "=f"(lo), "=f"(hi) : "l"(v));
    return make_float2(lo, hi);
}

// vectorized global float4 reduction (sm_90+)
__device__ __forceinline__ void red4(float* p, float a, float b, float c, float d) {
    asm volatile("red.global.add.v4.f32 [%0], {%1, %2, %3, %4};"
                 :: "l"(p), "f"(a), "f"(b), "f"(c), "f"(d) : "memory");
}

// ---------------- utility ----------------
__global__ void zero_kernel(float* p, int count) {
    int i = blockIdx.x * blockDim.x + threadIdx.x;
    for (; i < count; i += gridDim.x * blockDim.x) p[i] = 0.f;
}

// split-K reduce over 2 partials
__global__ void addhalf_kernel(const float* __restrict__ s, float* __restrict__ d, int count4) {
    int i = blockIdx.x * blockDim.x + threadIdx.x;
    if (i >= count4) return;
    const float4* a = reinterpret_cast<const float4*>(s);
    float4 x = a[i], y = a[i + count4];
    reinterpret_cast<float4*>(d)[i] = make_float4(x.x + y.x, x.y + y.y, x.z + y.z, x.w + y.w);
}

// ---------------- GCN degree ----------------
__global__ void deg_kernel(const int* __restrict__ ei, float* __restrict__ deg) {
    int i = blockIdx.x * blockDim.x + threadIdx.x;
    if (i < EDGES) atomicAdd(&deg[ei[EDGES + i]], 1.0f);
}
__global__ void inv_kernel(const float* __restrict__ deg, float* __restrict__ inv) {
    int i = blockIdx.x * blockDim.x + threadIdx.x;
    if (i < NN) inv[i] = rsqrtf(deg[i] + 1.0f);
}

// ---------------- high-throughput fp32x2 GEMM, optional split-K via gridDim.z ----------------
// C_z = A[M, klo:khi] * B[klo:khi, N] (+bias)(+relu), partial z written at C + z*M*N.
// BM=128, 256 threads. M%128==0, N%4==0, K%4==0, ksplit%16==0.
template<int BN, int TM, int TN, bool BIAS, bool RELU>
__global__ __launch_bounds__(256) void gemm_tc(
    const float* __restrict__ A, const float* __restrict__ B,
    const float* __restrict__ bias, float* __restrict__ C,
    int M, int N, int Kd, int ksplit)
{
    constexpr int BM = 128;
    constexpr int KS = 16;
    __shared__ __align__(16) float As[KS][BM + 4];
    __shared__ __align__(16) float Bs[KS][BN + 4];
    const int tid = threadIdx.x;
    const int mb = blockIdx.y * BM, nb = blockIdx.x * BN;
    const int tx = tid % (BN / TN);
    const int ty = tid / (BN / TN);
    const int klo = blockIdx.z * ksplit;
    const int khi = (klo + ksplit < Kd) ? (klo + ksplit) : Kd;
    float* Cw = C + (size_t)blockIdx.z * M * N;

    const int arow = tid >> 1;
    const int akseg = (tid & 1) * 8;
    const int bkk = tid >> 4;
    const int bcol = (tid & 15) * (BN / 16);
    constexpr int BVEC = BN / 64;

    unsigned long long acc2[TM / 2][TN] = {};

    for (int kb = klo; kb < khi; kb += KS) {
        #pragma unroll
        for (int v = 0; v < 2; v++) {
            int kk = akseg + v * 4;
            float4 va = make_float4(0.f, 0.f, 0.f, 0.f);
            if (kb + kk + 4 <= khi)
                va = *reinterpret_cast<const float4*>(A + (size_t)(mb + arow) * Kd + kb + kk);
            As[kk + 0][arow] = va.x;
            As[kk + 1][arow] = va.y;
            As[kk + 2][arow] = va.z;
            As[kk + 3][arow] = va.w;
        }
        #pragma unroll
        for (int v = 0; v < BVEC; v++) {
            int col = bcol + v * 4;
            float4 vb = make_float4(0.f, 0.f, 0.f, 0.f);
            if (kb + bkk < khi && nb + col < N)
                vb = *reinterpret_cast<const float4*>(B + (size_t)(kb + bkk) * N + nb + col);
            *reinterpret_cast<float4*>(&Bs[bkk][col]) = vb;
        }
        __syncthreads();

        #pragma unroll
        for (int kk = 0; kk < KS; kk++) {
            unsigned long long a2[TM / 2];
            #pragma unroll
            for (int i = 0; i < TM; i += 4) {
                ulonglong2 t = *reinterpret_cast<const ulonglong2*>(&As[kk][ty * TM + i]);
                a2[i / 2] = t.x;
                a2[i / 2 + 1] = t.y;
            }
            #pragma unroll
            for (int j = 0; j < TN; j += 4) {
                float4 t = *reinterpret_cast<const float4*>(&Bs[kk][tx * TN + j]);
                unsigned long long b0 = splat2(t.x), b1 = splat2(t.y);
                unsigned long long b2 = splat2(t.z), b3 = splat2(t.w);
                #pragma unroll
                for (int p = 0; p < TM / 2; p++) {
                    fma2(acc2[p][j + 0], a2[p], b0);
                    fma2(acc2[p][j + 1], a2[p], b1);
                    fma2(acc2[p][j + 2], a2[p], b2);
                    fma2(acc2[p][j + 3], a2[p], b3);
                }
            }
        }
        __syncthreads();
    }

    float accf[TM][TN];
    #pragma unroll
    for (int p = 0; p < TM / 2; p++)
        #pragma unroll
        for (int j = 0; j < TN; j++) {
            float2 f = unpack2(acc2[p][j]);
            accf[2 * p][j] = f.x;
            accf[2 * p + 1][j] = f.y;
        }

    #pragma unroll
    for (int i = 0; i < TM; i++) {
        int row = mb + ty * TM + i;
        #pragma unroll
        for (int j = 0; j < TN; j += 4) {
            int col = nb + tx * TN + j;
            if (col < N) {
                float4 v;
                v.x = accf[i][j];     v.y = accf[i][j + 1];
                v.z = accf[i][j + 2]; v.w = accf[i][j + 3];
                if (BIAS) {
                    float4 bsv = *reinterpret_cast<const float4*>(bias + col);
                    v.x += bsv.x; v.y += bsv.y; v.z += bsv.z; v.w += bsv.w;
                }
                if (RELU) {
                    v.x = fmaxf(v.x, 0.f); v.y = fmaxf(v.y, 0.f);
                    v.z = fmaxf(v.z, 0.f); v.w = fmaxf(v.w, 0.f);
                }
                *reinterpret_cast<float4*>(Cw + (size_t)row * N + col) = v;
            }
        }
    }
}

// ---------------- small generic tiled fp32 GEMM (N=64 GCN-2) ----------------
template<bool BIAS, bool RELU>
__global__ __launch_bounds__(256) void gemm_kernel(
    const float* __restrict__ A, const float* __restrict__ B,
    const float* __restrict__ bias, float* __restrict__ C,
    int M, int N, int Kd)
{
    __shared__ float As[16][65];
    __shared__ float Bs[16][64];
    int tid = threadIdx.x;
    int mb = blockIdx.y * 64, nb = blockIdx.x * 64;
    int tx = tid & 15, ty = tid >> 4;
    float acc[4][4] = {};
    for (int kb = 0; kb < Kd; kb += 16) {
        #pragma unroll
        for (int p = 0; p < 4; p++) {
            int idx = tid + p * 256;
            int m = idx >> 4, k = idx & 15;
            float v = 0.f;
            if (kb + k < Kd) v = A[(size_t)(mb + m) * Kd + kb + k];
            As[k][m] = v;
        }
        #pragma unroll
        for (int p = 0; p < 4; p++) {
            int idx = tid + p * 256;
            int k = idx >> 6, nn2 = idx & 63;
            float v = 0.f;
            if (kb + k < Kd && nb + nn2 < N) v = B[(size_t)(kb + k) * N + nb + nn2];
            Bs[k][nn2] = v;
        }
        __syncthreads();
        #pragma unroll
        for (int kk = 0; kk < 16; kk++) {
            float ra[4], rb[4];
            #pragma unroll
            for (int i = 0; i < 4; i++) ra[i] = As[kk][ty * 4 + i];
            #pragma unroll
            for (int j = 0; j < 4; j++) rb[j] = Bs[kk][tx * 4 + j];
            #pragma unroll
            for (int i = 0; i < 4; i++)
                #pragma unroll
                for (int j = 0; j < 4; j++)
                    acc[i][j] += ra[i] * rb[j];
        }
        __syncthreads();
    }
    #pragma unroll
    for (int i = 0; i < 4; i++) {
        int row = mb + ty * 4 + i;
        #pragma unroll
        for (int j = 0; j < 4; j++) {
            int col = nb + tx * 4 + j;
            if (col < N) {
                float v = acc[i][j];
                if (BIAS) v += bias[col];
                if (RELU) v = fmaxf(v, 0.f);
                C[(size_t)row * N + col] = v;
            }
        }
    }
}

// ---------------- edge aggregation (vectorized red.global.v4, EPB edges per block) ----------------
// blockDim = EPB * (Hd/4)
template<int EPB>
__global__ void agg_edge_kernel(const int* __restrict__ ei, const float* __restrict__ hlin,
                                const float* __restrict__ inv, float* __restrict__ agg, int Hd) {
    int q = Hd / 4;
    int le = threadIdx.x / q;
    int d4 = threadIdx.x % q;
    int e = blockIdx.x * EPB + le;
    int s = ei[e], d2 = ei[EDGES + e];
    float c = inv[s] * inv[d2];
    const float4* hr = reinterpret_cast<const float4*>(hlin + (size_t)s * Hd);
    float* ar = agg + (size_t)d2 * Hd;
    for (int d = d4; d < q; d += q) {   // single iteration; kept as loop for safety
        float4 v = hr[d];
        red4(ar + d * 4, v.x * c, v.y * c, v.z * c, v.w * c);
    }
}

template<bool RELU>
__global__ void combine_kernel(const float* __restrict__ agg, const float* __restrict__ hlin,
                               const float* __restrict__ inv, const float* __restrict__ bias,
                               float* __restrict__ out, int Hd) {
    int idx = blockIdx.x * blockDim.x + threadIdx.x;
    int total = NN * Hd;
    if (idx >= total) return;
    int n = idx / Hd, d = idx - n * Hd;
    float iv = inv[n];
    float v = agg[idx] + hlin[idx] * iv * iv + bias[d];
    if (RELU) v = fmaxf(v, 0.f);
    out[idx] = v;
}

// ---------------- niche mean pool ----------------
__global__ void niche_kernel(const int* __restrict__ sub, const float* __restrict__ spot,
                             float* __restrict__ local) {
    int n = blockIdx.x, d = threadIdx.x;
    float acc = 0.f;
    #pragma unroll
    for (int k = 0; k < KSUB; k++) {
        int idx = sub[n * KSUB + k];
        acc += spot[(size_t)idx * DD + d];
    }
    local[(size_t)n * DD + d] = acc * (1.0f / KSUB);
}

// ---------------- small linear (out = in @ W^T + b), W is [OUTD,64] row-major ----------------
__global__ void lin_t_kernel(const float* __restrict__ in, const float* __restrict__ W,
                             const float* __restrict__ b, float* __restrict__ out, int OUTD) {
    int nb = blockIdx.x * 32;
    int tid = threadIdx.x;  // OUTD threads
    __shared__ float xl[32][65];
    for (int i = tid; i < 32 * 64; i += blockDim.x)
        xl[i >> 6][i & 63] = in[(size_t)(nb + (i >> 6)) * 64 + (i & 63)];
    __syncthreads();
    float acc[32];
    #pragma unroll
    for (int nn2 = 0; nn2 < 32; nn2++) acc[nn2] = 0.f;
    for (int dd = 0; dd < 64; dd++) {
        float w = W[tid * 64 + dd];
        #pragma unroll
        for (int nn2 = 0; nn2 < 32; nn2++) acc[nn2] += xl[nn2][dd] * w;
    }
    float bb = b[tid];
    #pragma unroll
    for (int nn2 = 0; nn2 < 32; nn2++)
        out[(size_t)(nb + nn2) * OUTD + tid] = acc[nn2] + bb;
}

// ---------------- attention scores + per-tile (max, expsum) partials ----------------
__global__ __launch_bounds__(256) void scores_kernel(const float* __restrict__ qkv,
                                                     float* __restrict__ scores,
                                                     float* __restrict__ pmax,
                                                     float* __restrict__ psum) {
    int h = blockIdx.z;
    int qb = blockIdx.y * 64, mb = blockIdx.x * 64;
    __shared__ float qs[16][65], ks[16][65];
    int tid = threadIdx.x;
    #pragma unroll
    for (int p = 0; p < 4; p++) {
        int idx = tid + p * 256;
        int row = idx >> 4, kk = idx & 15;
        qs[kk][row] = qkv[(size_t)(qb + row) * 192 + h * 16 + kk];
        ks[kk][row] = qkv[(size_t)(mb + row) * 192 + 64 + h * 16 + kk];
    }
    __syncthreads();
    int tx = tid & 15, ty = tid >> 4;
    float acc[4][4] = {};
    #pragma unroll
    for (int kk = 0; kk < 16; kk++) {
        float ra[4], rb[4];
        #pragma unroll
        for (int i = 0; i < 4; i++) ra[i] = qs[kk][ty * 4 + i];
        #pragma unroll
        for (int j = 0; j < 4; j++) rb[j] = ks[kk][tx * 4 + j];
        #pragma unroll
        for (int i = 0; i < 4; i++)
            #pragma unroll
            for (int j = 0; j < 4; j++)
                acc[i][j] += ra[i] * rb[j];
    }
    #pragma unroll
    for (int i = 0; i < 4; i++) {
        float rmx = -1e30f;
        #pragma unroll
        for (int j = 0; j < 4; j++) {
            float s = acc[i][j] * 0.25f;
            acc[i][j] = s;
            rmx = fmaxf(rmx, s);
            scores[((size_t)(qb + ty * 4 + i) * 4 + h) * 4096 + mb + tx * 4 + j] = s;
        }
        #pragma unroll
        for (int off = 8; off > 0; off >>= 1)
            rmx = fmaxf(rmx, __shfl_xor_sync(0xffffffffu, rmx, off));
        float es = 0.f;
        #pragma unroll
        for (int j = 0; j < 4; j++) es += __expf(acc[i][j] - rmx);
        #pragma unroll
        for (int off = 8; off > 0; off >>= 1)
            es += __shfl_xor_sync(0xffffffffu, es, off);
        if (tx == 0) {
            int row = (qb + ty * 4 + i) * 4 + h;
            pmax[blockIdx.x * NROWS + row] = rmx;
            psum[blockIdx.x * NROWS + row] = es;
        }
    }
}

// ---------------- merge per-tile partials -> exact rmax + denominator ----------------
__global__ void smcombine_kernel(const float* __restrict__ pmax, const float* __restrict__ psum,
                                 float* __restrict__ rmax, float* __restrict__ rsum) {
    int row = blockIdx.x * blockDim.x + threadIdx.x;
    if (row >= NROWS) return;
    float M = -1e30f;
    #pragma unroll 8
    for (int t = 0; t < MTILES; t++) M = fmaxf(M, pmax[t * NROWS + row]);
    float S = 0.f;
    #pragma unroll 8
    for (int t = 0; t < MTILES; t++)
        S += psum[t * NROWS + row] * __expf(pmax[t * NROWS + row] - M);
    rmax[row] = M;
    rsum[row] = S;
}

// ---------------- fused probs + attn_w + AV (exp on the fly from raw scores) ----------------
__global__ __launch_bounds__(256) void probav_kernel(
    const float* __restrict__ qkv, const float* __restrict__ scores,
    const float* __restrict__ rmax, const float* __restrict__ rsum,
    float* __restrict__ attnw, float* __restrict__ attnpre)
{
    int qb = blockIdx.x * 16;
    int tid = threadIdx.x;
    __shared__ float vs[64][65];
    __shared__ float ps[16 * 4 * 64];   // [q][h][m]
    __shared__ float rm[64], ri[64];
    if (tid < 64) {
        int q = tid >> 2, h2 = tid & 3;
        rm[q * 4 + h2] = rmax[(qb + q) * 4 + h2];
        ri[q * 4 + h2] = 1.0f / rsum[(qb + q) * 4 + h2];
    }
    int d = tid & 63, g = tid >> 6;
    int h = d >> 4;
    float acc[4] = {0.f, 0.f, 0.f, 0.f};
    __syncthreads();
    for (int mb = 0; mb < 4096; mb += 64) {
        #pragma unroll
        for (int p = 0; p < 16; p++) {
            int i = tid + p * 256;
            vs[i >> 6][i & 63] = qkv[(size_t)(mb + (i >> 6)) * 192 + 128 + (i & 63)];
        }
        int m = tid & 63;
        #pragma unroll
        for (int j = 0; j < 4; j++) {
            int q = j * 4 + (tid >> 6);
            float aw = 0.f;
            #pragma unroll
            for (int hh = 0; hh < 4; hh++) {
                float s = scores[((size_t)(qb + q) * 4 + hh) * 4096 + mb + m];
                float p = __expf(s - rm[q * 4 + hh]) * ri[q * 4 + hh];
                ps[(q * 4 + hh) * 64 + m] = p;
                aw += p;
            }
            attnw[(size_t)(qb + q) * 4096 + mb + m] = aw * 0.25f;
        }
        __syncthreads();
        #pragma unroll 4
        for (int mm = 0; mm < 64; mm++) {
            float v = vs[mm][d];
            #pragma unroll
            for (int i = 0; i < 4; i++)
                acc[i] += ps[((i * 4 + g) * 4 + h) * 64 + mm] * v;
        }
        __syncthreads();
    }
    #pragma unroll
    for (int i = 0; i < 4; i++)
        attnpre[(size_t)(qb + i * 4 + g) * 64 + d] = acc[i];
}

// ---------------- threefry2x32 (matches JAX) ----------------
__device__ __forceinline__ unsigned rotl32(unsigned x, int r) { return (x << r) | (x >> (32 - r)); }
__device__ void threefry2x32(unsigned ks0, unsigned ks1, unsigned& x0, unsigned& x1) {
    unsigned ks2 = 0x1BD11BDAu ^ ks0 ^ ks1;
    x0 += ks0; x1 += ks1;
#define TFR(r) { x0 += x1; x1 = rotl32(x1, r); x1 ^= x0; }
    TFR(13) TFR(15) TFR(26) TFR(6)
    x0 += ks1; x1 += ks2 + 1u;
    TFR(17) TFR(29) TFR(16) TFR(24)
    x0 += ks2; x1 += ks0 + 2u;
    TFR(13) TFR(15) TFR(26) TFR(6)
    x0 += ks0; x1 += ks1 + 3u;
    TFR(17) TFR(29) TFR(16) TFR(24)
    x0 += ks1; x1 += ks2 + 4u;
    TFR(13) TFR(15) TFR(26) TFR(6)
    x0 += ks2; x1 += ks0 + 5u;
#undef TFR
}

// rand_idx = jax.random.randint(key(42), (4096,), 0, 1024)
__global__ void randidx_kernel(int* __restrict__ out) {
    int i = blockIdx.x * blockDim.x + threadIdx.x;
    if (i >= NN) return;
    unsigned a0 = 0u, b0 = 2u; threefry2x32(0u, 42u, a0, b0);
    unsigned a1 = 1u, b1 = 3u; threefry2x32(0u, 42u, a1, b1);
    unsigned k2a = b0, k2b = b1;
    unsigned x0, x1;
    if (i < 2048) { x0 = (unsigned)i; x1 = (unsigned)(i + 2048); }
    else          { x0 = (unsigned)(i - 2048); x1 = (unsigned)i; }
    threefry2x32(k2a, k2b, x0, x1);
    unsigned bits = (i < 2048) ? x0 : x1;
    out[i] = (int)(bits & 1023u);
}

// ---------------- per-row rank-select (radix select on float bits, stable ties) ----------------
__global__ __launch_bounds__(256) void select_kernel(const float* __restrict__ attnw,
                                                     const int* __restrict__ ridx,
                                                     int* __restrict__ sampled) {
    int n = blockIdx.x;
    int tid = threadIdx.x;  // 256
    __shared__ unsigned sk[4096];
    __shared__ int hist[256];
    __shared__ int bcast[2];
    __shared__ int warpcnt[8];
    __shared__ int running;
    const float* row = attnw + (size_t)n * 4096;
    for (int i = tid; i < 4096; i += 256) sk[i] = __float_as_uint(row[i]);
    int rr = ridx[n];
    unsigned prefix = 0;
    __syncthreads();
    for (int shift = 24; shift >= 0; shift -= 8) {
        hist[tid] = 0;
        __syncthreads();
        for (int i = tid; i < 4096; i += 256) {
            unsigned u = sk[i];
            bool match = (shift == 24) || ((u >> (shift + 8)) == prefix);
            if (match) atomicAdd(&hist[(u >> shift) & 255], 1);
        }
        __syncthreads();
        if (tid == 0) {
            int cum = 0; int b = 0;
            for (; b < 256; b++) { int c = hist[b]; if (cum + c > rr) break; cum += c; }
            bcast[0] = b; bcast[1] = rr - cum;
        }
        __syncthreads();
        prefix = (prefix << 8) | (unsigned)bcast[0];
        rr = bcast[1];
        __syncthreads();
    }
    if (tid == 0) running = 0;
    __syncthreads();
    int lane = tid & 31, wid = tid >> 5;
    for (int base = 0; base < 4096; base += 256) {
        int i = base + tid;
        bool m2 = (sk[i] == prefix);
        unsigned bal = __ballot_sync(0xffffffffu, m2);
        if (lane == 0) warpcnt[wid] = __popc(bal);
        __syncthreads();
        int wpre = 0, tot = 0;
        #pragma unroll
        for (int w = 0; w < 8; w++) { int c = warpcnt[w]; if (w < wid) wpre += c; tot += c; }
        int ord = running + wpre + __popc(bal & ((1u << lane) - 1u));
        if (m2 && ord == rr) sampled[n] = i;
        __syncthreads();
        if (tid == 0) running += tot;
        __syncthreads();
    }
}

// ---------------- bilinear discriminator logits ----------------
__global__ void bilinear_kernel(const float* __restrict__ local, const float* __restrict__ bw,
                                const float* __restrict__ bb, const float* __restrict__ glob,
                                const int* __restrict__ sampled,
                                float* __restrict__ lpos, float* __restrict__ lneg) {
    int n = blockIdx.x, e = threadIdx.x;  // 64
    __shared__ float l[64], red[64];
    l[e] = local[(size_t)n * 64 + e];
    __syncthreads();
    float t = 0.f;
    #pragma unroll
    for (int dd = 0; dd < 64; dd++) t += l[dd] * bw[dd * 64 + e];
    int s = sampled[n];
    float p = t * glob[(size_t)n * 64 + e];
    float q = t * glob[(size_t)s * 64 + e];
    red[e] = p; __syncthreads();
    for (int off = 32; off > 0; off >>= 1) { if (e < off) red[e] += red[e + off]; __syncthreads(); }
    if (e == 0) lpos[n] = red[0] + bb[0];
    __syncthreads();
    red[e] = q; __syncthreads();
    for (int off = 32; off > 0; off >>= 1) { if (e < off) red[e] += red[e + off]; __syncthreads(); }
    if (e == 0) lneg[n] = red[0] + bb[0];
}

// ---------------- launcher ----------------
extern "C" void kernel_launch(void* const* d_in, const int* in_sizes, int n_in,
                              void* d_out, int out_size) {
    const float* x    = (const float*)d_in[0];
    const int*   ei   = (const int*)d_in[1];
    const int*   sub  = (const int*)d_in[2];
    const float* ew1  = (const float*)d_in[3];
    const float* eb1  = (const float*)d_in[4];
    const float* ew2  = (const float*)d_in[5];
    const float* eb2  = (const float*)d_in[6];
    const float* dw1  = (const float*)d_in[7];
    const float* db1  = (const float*)d_in[8];
    const float* dw2  = (const float*)d_in[9];
    const float* db2  = (const float*)d_in[10];
    const float* aiw  = (const float*)d_in[11];
    const float* aib  = (const float*)d_in[12];
    const float* aow  = (const float*)d_in[13];
    const float* aob  = (const float*)d_in[14];
    const float* bw   = (const float*)d_in[15];
    const float* bb   = (const float*)d_in[16];

    float* out   = (float*)d_out;
    float* recon = out;
    float* lpos  = out + (size_t)RECON_ELEMS;
    float* lneg  = out + (size_t)RECON_ELEMS + NN;

    float *p_deg, *p_inv, *p_hsplit, *p_hlin, *p_agg1, *p_h, *p_slin, *p_agg2, *p_spot, *p_local;
    float *p_hdec, *p_qkv, *p_scores, *p_attnw, *p_pmax, *p_psum, *p_rmax, *p_rsum;
    float *p_attnpre, *p_global;
    int *p_ridx, *p_samp;
    cudaGetSymbolAddress((void**)&p_deg, g_deg);
    cudaGetSymbolAddress((void**)&p_inv, g_inv);
    cudaGetSymbolAddress((void**)&p_hsplit, g_hsplit);
    cudaGetSymbolAddress((void**)&p_hlin, g_hlin);
    cudaGetSymbolAddress((void**)&p_agg1, g_agg1);
    cudaGetSymbolAddress((void**)&p_h, g_h);
    cudaGetSymbolAddress((void**)&p_slin, g_slin);
    cudaGetSymbolAddress((void**)&p_agg2, g_agg2);
    cudaGetSymbolAddress((void**)&p_spot, g_spot);
    cudaGetSymbolAddress((void**)&p_local, g_local);
    cudaGetSymbolAddress((void**)&p_hdec, g_hdec);
    cudaGetSymbolAddress((void**)&p_qkv, g_qkv);
    cudaGetSymbolAddress((void**)&p_scores, g_scores);
    cudaGetSymbolAddress((void**)&p_attnw, g_attnw);
    cudaGetSymbolAddress((void**)&p_pmax, g_pmax);
    cudaGetSymbolAddress((void**)&p_psum, g_psum);
    cudaGetSymbolAddress((void**)&p_rmax, g_rmax);
    cudaGetSymbolAddress((void**)&p_rsum, g_rsum);
    cudaGetSymbolAddress((void**)&p_attnpre, g_attnpre);
    cudaGetSymbolAddress((void**)&p_global, g_global);
    cudaGetSymbolAddress((void**)&p_ridx, g_randidx);
    cudaGetSymbolAddress((void**)&p_samp, g_sampled);

    // launches 1..3: zero accumulators (every replay)
    zero_kernel<<<4096, 256>>>(p_agg1, NN * H1);
    zero_kernel<<<1024, 256>>>(p_agg2, NN * DD);
    zero_kernel<<<16, 256>>>(p_deg, NN);

    // launch 4 (profiled slot): encoder GEMM — R14 champion config (BN=64, split-K=2)
    gemm_tc<64, 8, 4, false, false><<<dim3(H1 / 64, NN / 128, 2), 256>>>(
        x, ew1, nullptr, p_hsplit, NN, H1, IN_DIM, 1504);
    addhalf_kernel<<<(NN * H1 / 4 + 255) / 256, 256>>>(p_hsplit, p_hlin, NN * H1 / 4);

    // degrees
    deg_kernel<<<(EDGES + 255) / 256, 256>>>(ei, p_deg);
    inv_kernel<<<(NN + 255) / 256, 256>>>(p_deg, p_inv);

    // GCN layer 1 aggregation (red.v4)
    agg_edge_kernel<1><<<EDGES, 128>>>(ei, p_hlin, p_inv, p_agg1, H1);
    combine_kernel<true><<<(NN * H1 + 255) / 256, 256>>>(p_agg1, p_hlin, p_inv, eb1, p_h, H1);

    // GCN layer 2
    gemm_kernel<false, false><<<dim3(1, NN / 64), 256>>>(p_h, ew2, nullptr, p_slin, NN, DD, H1);
    agg_edge_kernel<8><<<EDGES / 8, 128>>>(ei, p_slin, p_inv, p_agg2, DD);
    combine_kernel<false><<<(NN * DD + 255) / 256, 256>>>(p_agg2, p_slin, p_inv, eb2, p_spot, DD);

    // niche mean pool
    niche_kernel<<<NN, DD>>>(sub, p_spot, p_local);

    // decoder
    gemm_tc<64, 8, 4, true, true><<<dim3(H1 / 64, NN / 128, 1), 256>>>(
        p_local, dw1, db1, p_hdec, NN, H1, DD, DD);
    gemm_tc<64, 8, 4, true, false><<<dim3((IN_DIM + 63) / 64, NN / 128, 1), 256>>>(
        p_hdec, dw2, db2, recon, NN, IN_DIM, H1, H1);

    // attention (materialized scores; per-tile softmax partials)
    lin_t_kernel<<<NN / 32, 192>>>(p_local, aiw, aib, p_qkv, 192);
    scores_kernel<<<dim3(64, 64, 4), 256>>>(p_qkv, p_scores, p_pmax, p_psum);
    smcombine_kernel<<<(NROWS + 255) / 256, 256>>>(p_pmax, p_psum, p_rmax, p_rsum);
    probav_kernel<<<NN / 16, 256>>>(p_qkv, p_scores, p_rmax, p_rsum, p_attnw, p_attnpre);
    lin_t_kernel<<<NN / 32, 64>>>(p_attnpre, aow, aob, p_global, 64);

    // negative sampling + logits
    randidx_kernel<<<(NN + 255) / 256, 256>>>(p_ridx);
    select_kernel<<<NN, 256>>>(p_attnw, p_ridx, p_samp);
    bilinear_kernel<<<NN, 64>>>(p_local, bw, bb, p_global, p_samp, lpos, lneg);
}